// round 3
// baseline (speedup 1.0000x reference)
#include <cuda_runtime.h>
#include <cuda_bf16.h>

// NLL sequence loss: only the last valid timestep per batch row contributes.
//   loss = -(1/B) * sum_b inputs[b, min(T,length[b])-1, target[b]]
//
// 8 warps x 64 gathers/warp (2 per thread): every gather is issued before any
// completion is needed, so all 512 scattered loads overlap in a single
// DRAM/L2 latency round (per-warp outstanding-load cap ~55 is not the
// binding constraint at 64/warp split over 2 program-order loads).
// Reduction: in-register add, warp shuffle, 8-word smem, final warp shuffle.

#define B_DIM 512
#define T_DIM 128
#define C_DIM 2000
#define NTHREADS 256
#define RPT 2   // rows per thread

__global__ __launch_bounds__(NTHREADS, 1)
void nll_seq_loss_kernel(const float* __restrict__ inputs,
                         const int*   __restrict__ length,
                         const int*   __restrict__ target,
                         float*       __restrict__ out) {
    const int t = threadIdx.x;

    // Two rows per thread: rows t and t+256 (coalesced int loads for both).
    int len0 = length[t];
    int len1 = length[t + NTHREADS];
    int tgt0 = target[t];
    int tgt1 = target[t + NTHREADS];

    int last0 = (len0 < T_DIM ? len0 : T_DIM) - 1;
    int last1 = (len1 < T_DIM ? len1 : T_DIM) - 1;

    // Row stride T*C = 256000 elements; all indices < 2^31.
    int idx0 = (t            * T_DIM + last0) * C_DIM + tgt0;
    int idx1 = ((t + NTHREADS) * T_DIM + last1) * C_DIM + tgt1;

    float v0 = __ldg(inputs + idx0);
    float v1 = __ldg(inputs + idx1);
    float s = v0 + v1;

    // Warp reduction.
    #pragma unroll
    for (int off = 16; off > 0; off >>= 1)
        s += __shfl_down_sync(0xFFFFFFFFu, s, off);

    __shared__ float warp_sums[NTHREADS / 32];
    const int lane = t & 31;
    const int wid  = t >> 5;
    if (lane == 0) warp_sums[wid] = s;
    __syncthreads();

    if (wid == 0) {
        float w = (lane < (NTHREADS / 32)) ? warp_sums[lane] : 0.0f;
        #pragma unroll
        for (int off = 4; off > 0; off >>= 1)
            w += __shfl_down_sync(0xFFFFFFFFu, w, off);
        if (lane == 0)
            out[0] = -w * (1.0f / (float)B_DIM);
    }
}

extern "C" void kernel_launch(void* const* d_in, const int* in_sizes, int n_in,
                              void* d_out, int out_size) {
    const float* inputs = (const float*)d_in[0];
    const int*   length = (const int*)d_in[1];
    const int*   target = (const int*)d_in[2];
    float*       out    = (float*)d_out;

    nll_seq_loss_kernel<<<1, NTHREADS>>>(inputs, length, target, out);
}

// round 4
// speedup vs baseline: 1.0721x; 1.0721x over previous
#include <cuda_runtime.h>
#include <cuda_bf16.h>

// NLL sequence loss: only the last valid timestep per batch row contributes.
//   loss = -(1/B) * sum_b inputs[b, min(T,length[b])-1, target[b]]
//
// Minimal-critical-path variant: 4 warps x 4 rows/thread.
//  - length/target read as one int4 per array per thread (one memory round).
//  - 4 independent gathers per thread issue back-to-back (full MLP overlap;
//    one L2/DRAM latency round for all 512 gathers chip-wide).
//  - Reduction: 3 register adds -> 5 warp shuffles -> 4-word smem -> 2 shuffles.
// Bench is floored at ~6.9us of graph-replay/launch overhead; kernel body is
// ~0.3us warm. This is the converged form.

#define B_DIM 512
#define T_DIM 128
#define C_DIM 2000
#define NTHREADS 128
#define RPT 4   // rows per thread = B_DIM / NTHREADS

__global__ __launch_bounds__(NTHREADS, 1)
void nll_seq_loss_kernel(const float* __restrict__ inputs,
                         const int*   __restrict__ length,
                         const int*   __restrict__ target,
                         float*       __restrict__ out) {
    const int t = threadIdx.x;
    const int base = t * RPT;   // contiguous 4-row chunk -> aligned int4

    int4 l = *(const int4*)(length + base);
    int4 g = *(const int4*)(target + base);

    int len[RPT] = {l.x, l.y, l.z, l.w};
    int tgt[RPT] = {g.x, g.y, g.z, g.w};

    float v[RPT];
    #pragma unroll
    for (int j = 0; j < RPT; j++) {
        int last = (len[j] < T_DIM ? len[j] : T_DIM) - 1;
        int idx = ((base + j) * T_DIM + last) * C_DIM + tgt[j];
        v[j] = __ldg(inputs + idx);
    }

    float s = (v[0] + v[1]) + (v[2] + v[3]);

    #pragma unroll
    for (int off = 16; off > 0; off >>= 1)
        s += __shfl_down_sync(0xFFFFFFFFu, s, off);

    __shared__ float warp_sums[NTHREADS / 32];
    const int lane = t & 31;
    const int wid  = t >> 5;
    if (lane == 0) warp_sums[wid] = s;
    __syncthreads();

    if (wid == 0) {
        float w = (lane < (NTHREADS / 32)) ? warp_sums[lane] : 0.0f;
        #pragma unroll
        for (int off = 2; off > 0; off >>= 1)
            w += __shfl_down_sync(0xFFFFFFFFu, w, off);
        if (lane == 0)
            out[0] = -w * (1.0f / (float)B_DIM);
    }
}

extern "C" void kernel_launch(void* const* d_in, const int* in_sizes, int n_in,
                              void* d_out, int out_size) {
    const float* inputs = (const float*)d_in[0];
    const int*   length = (const int*)d_in[1];
    const int*   target = (const int*)d_in[2];
    float*       out    = (float*)d_out;

    nll_seq_loss_kernel<<<1, NTHREADS>>>(inputs, length, target, out);
}